// round 1
// baseline (speedup 1.0000x reference)
#include <cuda_runtime.h>

// Fused transformer block: B=262144, T=8, C=32, heads=4, head=8, FF=128, fp32.
// One warp per batch item. All weights repacked into shared (float4, lane-major).
//
// Shared layout (floats):
//   sWa [4096]  : [c][lane][4] = (Wk, Wq*scale, Wv, pad), lane=(h,d)
//   sWp [1024]  : [ci4][lane][4] = Wp[ci4*4+i][lane]
//   sW1 [4096]  : [ci][lane][4]  = W1[ci][k*32+lane]
//   sW2 [4096]  : [f4][lane][4]  = W2[f4*4+i][lane]
//   per-warp scratch 1536 floats: sX[256], sX1[256], {sK,sQ,sV,sA}[1024] (overlaid by sH[1024])

#define WARPS_PER_BLOCK 8
#define THREADS_PER_BLOCK 256
#define GRID_BLOCKS 2048

#define SMEM_FLOATS (13312 + WARPS_PER_BLOCK * 1536)
#define SMEM_BYTES  (SMEM_FLOATS * 4)

__global__ __launch_bounds__(THREADS_PER_BLOCK, 2)
void tblock_kernel(const float* __restrict__ X,
                   const float* __restrict__ Wa,
                   const float* __restrict__ Wp,
                   const float* __restrict__ W1,
                   const float* __restrict__ W2,
                   float* __restrict__ Out,
                   int NB)
{
    extern __shared__ float sm[];
    float* const sWa = sm;            // 4096
    float* const sWp = sm + 4096;     // 1024
    float* const sW1 = sm + 5120;     // 4096
    float* const sW2 = sm + 9216;     // 4096
    float* const scr = sm + 13312;

    const int tid  = threadIdx.x;
    const int warp = tid >> 5;
    const int lane = tid & 31;

    const float scale = 0.17677669529663687f;   // 32^{-1/2} (full embed dim, per reference)

    // ---------------- pack weights into shared ----------------
    for (int idx = tid; idx < 1024; idx += THREADS_PER_BLOCK) {
        int c = idx >> 5, l = idx & 31;
        int h = l >> 3, d = l & 7;
        const float* w = Wa + h * 768 + c * 24 + d;     // [h][c][24], order K,Q,V
        *(float4*)&sWa[(c << 7) + (l << 2)] =
            make_float4(w[0], w[8] * scale, w[16], 0.0f);
    }
    for (int idx = tid; idx < 256; idx += THREADS_PER_BLOCK) {
        int ci4 = idx >> 5, l = idx & 31;
        *(float4*)&sWp[(ci4 << 7) + (l << 2)] =
            make_float4(Wp[(ci4 * 4 + 0) * 32 + l], Wp[(ci4 * 4 + 1) * 32 + l],
                        Wp[(ci4 * 4 + 2) * 32 + l], Wp[(ci4 * 4 + 3) * 32 + l]);
    }
    for (int idx = tid; idx < 1024; idx += THREADS_PER_BLOCK) {
        int ci = idx >> 5, l = idx & 31;
        *(float4*)&sW1[(ci << 7) + (l << 2)] =
            make_float4(W1[ci * 128 + l],      W1[ci * 128 + 32 + l],
                        W1[ci * 128 + 64 + l], W1[ci * 128 + 96 + l]);
    }
    for (int idx = tid; idx < 1024; idx += THREADS_PER_BLOCK) {
        int f4 = idx >> 5, l = idx & 31;
        *(float4*)&sW2[(f4 << 7) + (l << 2)] =
            make_float4(W2[(f4 * 4 + 0) * 32 + l], W2[(f4 * 4 + 1) * 32 + l],
                        W2[(f4 * 4 + 2) * 32 + l], W2[(f4 * 4 + 3) * 32 + l]);
    }
    __syncthreads();

    float* const buf = scr + warp * 1536;
    float* const sX  = buf;            // 256: X tile [t*32+c], reused for output staging
    float* const sX1 = buf + 256;      // 256: post-attention residual
    float* const sK  = buf + 512;      // 256 [t*32 + h*8+d]
    float* const sQ  = buf + 768;      // 256
    float* const sV  = buf + 1024;     // 256
    float* const sA  = buf + 1280;     // 256: attention output [t*32+c]
    float* const sH  = buf + 512;      // 1024: FF hidden [t*128+f] (overlays K,Q,V,A)

    const int h3 = lane >> 3;          // attention-stage head
    const int qt = lane & 7;           // attention-stage query row

    for (int b = blockIdx.x * WARPS_PER_BLOCK + warp; b < NB;
         b += GRID_BLOCKS * WARPS_PER_BLOCK) {
        const float* xg = X + (long long)b * 256;

        // ---- load X tile (vectorized, coalesced) ----
        *(float4*)&sX[lane * 8]     = *(const float4*)(xg + lane * 8);
        *(float4*)&sX[lane * 8 + 4] = *(const float4*)(xg + lane * 8 + 4);
        __syncwarp();

        // ---- stage 2: fused QKV. lane = (h, d) == lane index ----
        float kk[8], qq[8], vv[8];
        #pragma unroll
        for (int t = 0; t < 8; t++) { kk[t] = 0.f; qq[t] = 0.f; vv[t] = 0.f; }
        #pragma unroll 1
        for (int c4 = 0; c4 < 8; c4++) {
            const float4 w0 = *(float4*)&sWa[(c4 * 4 + 0) * 128 + lane * 4];
            const float4 w1 = *(float4*)&sWa[(c4 * 4 + 1) * 128 + lane * 4];
            const float4 w2 = *(float4*)&sWa[(c4 * 4 + 2) * 128 + lane * 4];
            const float4 w3 = *(float4*)&sWa[(c4 * 4 + 3) * 128 + lane * 4];
            #pragma unroll
            for (int t = 0; t < 8; t++) {
                const float4 x4 = *(float4*)&sX[t * 32 + c4 * 4];
                kk[t] = fmaf(x4.x, w0.x, kk[t]);
                kk[t] = fmaf(x4.y, w1.x, kk[t]);
                kk[t] = fmaf(x4.z, w2.x, kk[t]);
                kk[t] = fmaf(x4.w, w3.x, kk[t]);
                qq[t] = fmaf(x4.x, w0.y, qq[t]);
                qq[t] = fmaf(x4.y, w1.y, qq[t]);
                qq[t] = fmaf(x4.z, w2.y, qq[t]);
                qq[t] = fmaf(x4.w, w3.y, qq[t]);
                vv[t] = fmaf(x4.x, w0.z, vv[t]);
                vv[t] = fmaf(x4.y, w1.z, vv[t]);
                vv[t] = fmaf(x4.z, w2.z, vv[t]);
                vv[t] = fmaf(x4.w, w3.z, vv[t]);
            }
        }
        #pragma unroll
        for (int t = 0; t < 8; t++) {
            sK[t * 32 + lane] = kk[t];
            sQ[t * 32 + lane] = qq[t];
            sV[t * 32 + lane] = vv[t];
        }
        __syncwarp();

        // ---- stage 3: attention. lane = (h3, qt). scale folded into Q ----
        const float4 qa = *(float4*)&sQ[qt * 32 + h3 * 8];
        const float4 qb = *(float4*)&sQ[qt * 32 + h3 * 8 + 4];
        float e[8];
        float mx = -1e30f;
        #pragma unroll
        for (int kt = 0; kt < 8; kt++) {
            const float4 ka = *(float4*)&sK[kt * 32 + h3 * 8];
            const float4 kb = *(float4*)&sK[kt * 32 + h3 * 8 + 4];
            float acc = qa.x * ka.x;
            acc = fmaf(qa.y, ka.y, acc);
            acc = fmaf(qa.z, ka.z, acc);
            acc = fmaf(qa.w, ka.w, acc);
            acc = fmaf(qb.x, kb.x, acc);
            acc = fmaf(qb.y, kb.y, acc);
            acc = fmaf(qb.z, kb.z, acc);
            acc = fmaf(qb.w, kb.w, acc);
            e[kt] = (kt <= qt) ? acc : -1e30f;   // causal mask
            mx = fmaxf(mx, e[kt]);
        }
        float sum = 0.f;
        #pragma unroll
        for (int kt = 0; kt < 8; kt++) {
            e[kt] = __expf(e[kt] - mx);          // masked -> exp(-huge) == 0
            sum += e[kt];
        }
        const float inv = __fdividef(1.0f, sum);
        float4 oa = make_float4(0.f, 0.f, 0.f, 0.f);
        float4 ob = make_float4(0.f, 0.f, 0.f, 0.f);
        #pragma unroll
        for (int kt = 0; kt < 8; kt++) {
            const float wgt = e[kt] * inv;
            const float4 va = *(float4*)&sV[kt * 32 + h3 * 8];
            const float4 vb = *(float4*)&sV[kt * 32 + h3 * 8 + 4];
            oa.x = fmaf(wgt, va.x, oa.x);
            oa.y = fmaf(wgt, va.y, oa.y);
            oa.z = fmaf(wgt, va.z, oa.z);
            oa.w = fmaf(wgt, va.w, oa.w);
            ob.x = fmaf(wgt, vb.x, ob.x);
            ob.y = fmaf(wgt, vb.y, ob.y);
            ob.z = fmaf(wgt, vb.z, ob.z);
            ob.w = fmaf(wgt, vb.w, ob.w);
        }
        *(float4*)&sA[qt * 32 + h3 * 8]     = oa;   // [t][c] layout, c = h*8+d
        *(float4*)&sA[qt * 32 + h3 * 8 + 4] = ob;
        __syncwarp();

        // ---- stage 4: proj + residual. lane = output channel ----
        float x1[8];
        #pragma unroll
        for (int t = 0; t < 8; t++) x1[t] = sX[t * 32 + lane];
        #pragma unroll 1
        for (int ci4 = 0; ci4 < 8; ci4++) {
            const float4 w = *(float4*)&sWp[ci4 * 128 + lane * 4];
            #pragma unroll
            for (int t = 0; t < 8; t++) {
                const float4 a4 = *(float4*)&sA[t * 32 + ci4 * 4];
                x1[t] = fmaf(a4.x, w.x, x1[t]);
                x1[t] = fmaf(a4.y, w.y, x1[t]);
                x1[t] = fmaf(a4.z, w.z, x1[t]);
                x1[t] = fmaf(a4.w, w.w, x1[t]);
            }
        }
        #pragma unroll
        for (int t = 0; t < 8; t++) sX1[t * 32 + lane] = x1[t];
        __syncwarp();

        // ---- stage 5: FF1 + relu. lane owns f = k*32+lane, k=0..3 ----
        float hacc[8][4];
        #pragma unroll
        for (int t = 0; t < 8; t++)
            #pragma unroll
            for (int k = 0; k < 4; k++) hacc[t][k] = 0.f;
        #pragma unroll 1
        for (int c4 = 0; c4 < 8; c4++) {
            const float4 wA = *(float4*)&sW1[(c4 * 4 + 0) * 128 + lane * 4];
            const float4 wB = *(float4*)&sW1[(c4 * 4 + 1) * 128 + lane * 4];
            const float4 wC = *(float4*)&sW1[(c4 * 4 + 2) * 128 + lane * 4];
            const float4 wD = *(float4*)&sW1[(c4 * 4 + 3) * 128 + lane * 4];
            #pragma unroll
            for (int t = 0; t < 8; t++) {
                const float4 x4 = *(float4*)&sX1[t * 32 + c4 * 4];
                hacc[t][0] = fmaf(x4.x, wA.x, hacc[t][0]);
                hacc[t][1] = fmaf(x4.x, wA.y, hacc[t][1]);
                hacc[t][2] = fmaf(x4.x, wA.z, hacc[t][2]);
                hacc[t][3] = fmaf(x4.x, wA.w, hacc[t][3]);
                hacc[t][0] = fmaf(x4.y, wB.x, hacc[t][0]);
                hacc[t][1] = fmaf(x4.y, wB.y, hacc[t][1]);
                hacc[t][2] = fmaf(x4.y, wB.z, hacc[t][2]);
                hacc[t][3] = fmaf(x4.y, wB.w, hacc[t][3]);
                hacc[t][0] = fmaf(x4.z, wC.x, hacc[t][0]);
                hacc[t][1] = fmaf(x4.z, wC.y, hacc[t][1]);
                hacc[t][2] = fmaf(x4.z, wC.z, hacc[t][2]);
                hacc[t][3] = fmaf(x4.z, wC.w, hacc[t][3]);
                hacc[t][0] = fmaf(x4.w, wD.x, hacc[t][0]);
                hacc[t][1] = fmaf(x4.w, wD.y, hacc[t][1]);
                hacc[t][2] = fmaf(x4.w, wD.z, hacc[t][2]);
                hacc[t][3] = fmaf(x4.w, wD.w, hacc[t][3]);
            }
        }
        #pragma unroll
        for (int t = 0; t < 8; t++)
            #pragma unroll
            for (int k = 0; k < 4; k++)
                sH[t * 128 + k * 32 + lane] = fmaxf(hacc[t][k], 0.f);
        __syncwarp();

        // ---- stage 6: FF2, accumulate into x1 (second residual) ----
        #pragma unroll 1
        for (int f4 = 0; f4 < 32; f4++) {
            const float4 w = *(float4*)&sW2[f4 * 128 + lane * 4];
            #pragma unroll
            for (int t = 0; t < 8; t++) {
                const float4 h4 = *(float4*)&sH[t * 128 + f4 * 4];
                x1[t] = fmaf(h4.x, w.x, x1[t]);
                x1[t] = fmaf(h4.y, w.y, x1[t]);
                x1[t] = fmaf(h4.z, w.z, x1[t]);
                x1[t] = fmaf(h4.w, w.w, x1[t]);
            }
        }

        // ---- stage output via shared (vectorized, coalesced) ----
        #pragma unroll
        for (int t = 0; t < 8; t++) sX[t * 32 + lane] = x1[t];
        __syncwarp();
        float* og = Out + (long long)b * 256;
        *(float4*)(og + lane * 8)     = *(float4*)&sX[lane * 8];
        *(float4*)(og + lane * 8 + 4) = *(float4*)&sX[lane * 8 + 4];
        __syncwarp();
    }
}

extern "C" void kernel_launch(void* const* d_in, const int* in_sizes, int n_in,
                              void* d_out, int out_size) {
    const float* X  = (const float*)d_in[0];
    const float* Wa = (const float*)d_in[1];
    const float* Wp = (const float*)d_in[2];
    const float* W1 = (const float*)d_in[3];
    const float* W2 = (const float*)d_in[4];
    float* Out = (float*)d_out;
    const int NB = in_sizes[0] / 256;   // 262144 batch items

    cudaFuncSetAttribute(tblock_kernel,
                         cudaFuncAttributeMaxDynamicSharedMemorySize, SMEM_BYTES);
    tblock_kernel<<<GRID_BLOCKS, THREADS_PER_BLOCK, SMEM_BYTES>>>(
        X, Wa, Wp, W1, W2, Out, NB);
}

// round 2
// speedup vs baseline: 1.0304x; 1.0304x over previous
#include <cuda_runtime.h>

// Fused transformer block: B=262144, T=8, C=32, heads=4, head=8, FF=128, fp32.
// One warp per batch item. Weights repacked in shared; fma.rn.f32x2 packed
// over the reduction dimension; attention scratch padded to stride 36 to
// kill quarter-warp bank conflicts.

#define WARPS_PER_BLOCK 8
#define THREADS_PER_BLOCK 256
#define GRID_BLOCKS 2048

// weights: sWkq 2048 | sWv 1024 | sWp 1024 | sW1 4096 | sW2 4096 = 12288 floats
// per-warp scratch: sX 256 | sX1 256 | sK/sQ/sV/sA 4*288 (sH 1024 overlays) = 1664
#define SCRATCH_FLOATS 1664
#define SMEM_FLOATS (12288 + WARPS_PER_BLOCK * SCRATCH_FLOATS)
#define SMEM_BYTES  (SMEM_FLOATS * 4)

typedef unsigned long long ull;

__device__ __forceinline__ ull pk(float lo, float hi) {
    ull r; asm("mov.b64 %0,{%1,%2};" : "=l"(r) : "f"(lo), "f"(hi)); return r;
}
__device__ __forceinline__ void fma2(ull& d, ull a, ull b) {
    asm("fma.rn.f32x2 %0,%1,%2,%3;" : "=l"(d) : "l"(a), "l"(b), "l"(d));
}
__device__ __forceinline__ float psum(ull v) {
    float lo, hi; asm("mov.b64 {%0,%1},%2;" : "=f"(lo), "=f"(hi) : "l"(v));
    return lo + hi;
}

__global__ __launch_bounds__(THREADS_PER_BLOCK, 2)
void tblock_kernel(const float* __restrict__ X,
                   const float* __restrict__ Wa,
                   const float* __restrict__ Wp,
                   const float* __restrict__ W1,
                   const float* __restrict__ W2,
                   float* __restrict__ Out,
                   int NB)
{
    extern __shared__ float sm[];
    float* const sWkq = sm;            // 2048: [cpair][lane][4] = (k0,k1,q0*s,q1*s)
    float* const sWv  = sm + 2048;     // 1024: [cpair][lane][2] = (v0,v1)
    float* const sWp  = sm + 3072;     // 1024: [ci4][lane][4]   = Wp[4a+i][lane]
    float* const sW1  = sm + 4096;     // 4096: [cpair][lane][8] = pairs per k
    float* const sW2  = sm + 8192;     // 4096: [f4][lane][4]    = W2[4a+i][lane]
    float* const scr  = sm + 12288;

    const int tid  = threadIdx.x;
    const int warp = tid >> 5;
    const int lane = tid & 31;

    const float scale = 0.17677669529663687f;   // 32^{-1/2}

    // ---------------- pack weights ----------------
    for (int idx = tid; idx < 512; idx += THREADS_PER_BLOCK) {
        int p = idx >> 5, l = idx & 31;
        int h = l >> 3, d = l & 7;
        const float* base = Wa + h * 768 + d;        // [h][c][24]: K=+0, Q=+8, V=+16
        int c0 = 2 * p, c1 = 2 * p + 1;
        sWkq[p * 128 + l * 4 + 0] = base[c0 * 24];
        sWkq[p * 128 + l * 4 + 1] = base[c1 * 24];
        sWkq[p * 128 + l * 4 + 2] = base[c0 * 24 + 8] * scale;
        sWkq[p * 128 + l * 4 + 3] = base[c1 * 24 + 8] * scale;
        sWv[p * 64 + l * 2 + 0]   = base[c0 * 24 + 16];
        sWv[p * 64 + l * 2 + 1]   = base[c1 * 24 + 16];
        // sW1: pairs over c for each of 4 output groups k
        for (int k = 0; k < 4; k++) {
            sW1[p * 256 + l * 8 + k * 2 + 0] = W1[c0 * 128 + k * 32 + l];
            sW1[p * 256 + l * 8 + k * 2 + 1] = W1[c1 * 128 + k * 32 + l];
        }
    }
    for (int idx = tid; idx < 256; idx += THREADS_PER_BLOCK) {
        int a = idx >> 5, l = idx & 31;
        *(float4*)&sWp[(a << 7) + (l << 2)] =
            make_float4(Wp[(a * 4 + 0) * 32 + l], Wp[(a * 4 + 1) * 32 + l],
                        Wp[(a * 4 + 2) * 32 + l], Wp[(a * 4 + 3) * 32 + l]);
    }
    for (int idx = tid; idx < 1024; idx += THREADS_PER_BLOCK) {
        int a = idx >> 5, l = idx & 31;
        *(float4*)&sW2[(a << 7) + (l << 2)] =
            make_float4(W2[(a * 4 + 0) * 32 + l], W2[(a * 4 + 1) * 32 + l],
                        W2[(a * 4 + 2) * 32 + l], W2[(a * 4 + 3) * 32 + l]);
    }
    __syncthreads();

    float* const buf = scr + warp * SCRATCH_FLOATS;
    float* const sX  = buf;            // 256 [t*32+c]
    float* const sX1 = buf + 256;      // 256
    float* const sK  = buf + 512;      // 288, stride 36
    float* const sQ  = buf + 800;      // 288
    float* const sV  = buf + 1088;     // 288
    float* const sA  = buf + 1376;     // 288, stride 36
    float* const sH  = buf + 512;      // 1024 [t*128+f], overlays K/Q/V/A

    const int h3 = lane >> 3;
    const int qt = lane & 7;
    const int ho = h3 * 8;

    for (int b = blockIdx.x * WARPS_PER_BLOCK + warp; b < NB;
         b += GRID_BLOCKS * WARPS_PER_BLOCK) {
        const float* xg = X + (long long)b * 256;

        *(float4*)&sX[lane * 8]     = *(const float4*)(xg + lane * 8);
        *(float4*)&sX[lane * 8 + 4] = *(const float4*)(xg + lane * 8 + 4);
        __syncwarp();

        // ---- QKV, packed over c-pairs. lane = (h,d) ----
        {
            ull k2[8], q2[8], v2[8];
            #pragma unroll
            for (int t = 0; t < 8; t++) { k2[t] = 0; q2[t] = 0; v2[t] = 0; }
            #pragma unroll 1
            for (int g = 0; g < 8; g++) {            // c-quad = 2 c-pairs
                const ulonglong2 wkq0 = *(const ulonglong2*)&sWkq[(2 * g) * 128 + lane * 4];
                const ull        wv0  = *(const ull*)&sWv[(2 * g) * 64 + lane * 2];
                const ulonglong2 wkq1 = *(const ulonglong2*)&sWkq[(2 * g + 1) * 128 + lane * 4];
                const ull        wv1  = *(const ull*)&sWv[(2 * g + 1) * 64 + lane * 2];
                #pragma unroll
                for (int t = 0; t < 8; t++) {
                    const ulonglong2 x2 = *(const ulonglong2*)&sX[t * 32 + g * 4];
                    fma2(k2[t], x2.x, wkq0.x);
                    fma2(q2[t], x2.x, wkq0.y);
                    fma2(v2[t], x2.x, wv0);
                    fma2(k2[t], x2.y, wkq1.x);
                    fma2(q2[t], x2.y, wkq1.y);
                    fma2(v2[t], x2.y, wv1);
                }
            }
            #pragma unroll
            for (int t = 0; t < 8; t++) {
                sK[t * 36 + lane] = psum(k2[t]);
                sQ[t * 36 + lane] = psum(q2[t]);
                sV[t * 36 + lane] = psum(v2[t]);
            }
        }
        __syncwarp();

        // ---- attention. lane = (h3, qt); scale folded into Q ----
        {
            const ulonglong2 qA = *(const ulonglong2*)&sQ[qt * 36 + ho];
            const ulonglong2 qB = *(const ulonglong2*)&sQ[qt * 36 + ho + 4];
            float e[8];
            float mx = -1e30f;
            #pragma unroll
            for (int kt = 0; kt < 8; kt++) {
                const ulonglong2 kA = *(const ulonglong2*)&sK[kt * 36 + ho];
                const ulonglong2 kB = *(const ulonglong2*)&sK[kt * 36 + ho + 4];
                ull a2 = 0;
                fma2(a2, qA.x, kA.x);
                fma2(a2, qA.y, kA.y);
                fma2(a2, qB.x, kB.x);
                fma2(a2, qB.y, kB.y);
                float acc = psum(a2);
                e[kt] = (kt <= qt) ? acc : -1e30f;
                mx = fmaxf(mx, e[kt]);
            }
            float sum = 0.f;
            #pragma unroll
            for (int kt = 0; kt < 8; kt++) { e[kt] = __expf(e[kt] - mx); sum += e[kt]; }
            const float inv = __fdividef(1.0f, sum);
            float4 oa = make_float4(0.f, 0.f, 0.f, 0.f);
            float4 ob = make_float4(0.f, 0.f, 0.f, 0.f);
            #pragma unroll
            for (int kt = 0; kt < 8; kt++) {
                const float wgt = e[kt] * inv;
                const float4 va = *(const float4*)&sV[kt * 36 + ho];
                const float4 vb = *(const float4*)&sV[kt * 36 + ho + 4];
                oa.x = fmaf(wgt, va.x, oa.x);
                oa.y = fmaf(wgt, va.y, oa.y);
                oa.z = fmaf(wgt, va.z, oa.z);
                oa.w = fmaf(wgt, va.w, oa.w);
                ob.x = fmaf(wgt, vb.x, ob.x);
                ob.y = fmaf(wgt, vb.y, ob.y);
                ob.z = fmaf(wgt, vb.z, ob.z);
                ob.w = fmaf(wgt, vb.w, ob.w);
            }
            *(float4*)&sA[qt * 36 + ho]     = oa;
            *(float4*)&sA[qt * 36 + ho + 4] = ob;
        }
        __syncwarp();

        // ---- proj + residual, packed over ci-pairs. lane = out channel ----
        float x1[8];
        {
            ull x1p[8];
            #pragma unroll
            for (int t = 0; t < 8; t++) x1p[t] = pk(sX[t * 32 + lane], 0.f);
            #pragma unroll 1
            for (int a = 0; a < 8; a++) {
                const ulonglong2 w = *(const ulonglong2*)&sWp[a * 128 + lane * 4];
                #pragma unroll
                for (int t = 0; t < 8; t++) {
                    const ulonglong2 a2 = *(const ulonglong2*)&sA[t * 36 + a * 4];
                    fma2(x1p[t], a2.x, w.x);
                    fma2(x1p[t], a2.y, w.y);
                }
            }
            #pragma unroll
            for (int t = 0; t < 8; t++) {
                x1[t] = psum(x1p[t]);
                sX1[t * 32 + lane] = x1[t];
            }
        }
        __syncwarp();

        // ---- FF1 + relu, packed over c-pairs, split by k-halves ----
        #pragma unroll 1
        for (int hv = 0; hv < 2; hv++) {
            ull h2a[8], h2b[8];
            #pragma unroll
            for (int t = 0; t < 8; t++) { h2a[t] = 0; h2b[t] = 0; }
            #pragma unroll 1
            for (int g = 0; g < 8; g++) {
                const ulonglong2 w0 = *(const ulonglong2*)&sW1[(2 * g) * 256 + lane * 8 + hv * 4];
                const ulonglong2 w1 = *(const ulonglong2*)&sW1[(2 * g + 1) * 256 + lane * 8 + hv * 4];
                #pragma unroll
                for (int t = 0; t < 8; t++) {
                    const ulonglong2 x2 = *(const ulonglong2*)&sX1[t * 32 + g * 4];
                    fma2(h2a[t], x2.x, w0.x);
                    fma2(h2b[t], x2.x, w0.y);
                    fma2(h2a[t], x2.y, w1.x);
                    fma2(h2b[t], x2.y, w1.y);
                }
            }
            #pragma unroll
            for (int t = 0; t < 8; t++) {
                sH[t * 128 + (2 * hv + 0) * 32 + lane] = fmaxf(psum(h2a[t]), 0.f);
                sH[t * 128 + (2 * hv + 1) * 32 + lane] = fmaxf(psum(h2b[t]), 0.f);
            }
        }
        __syncwarp();

        // ---- FF2 + residual, packed over f-pairs ----
        {
            ull x1p[8];
            #pragma unroll
            for (int t = 0; t < 8; t++) x1p[t] = pk(x1[t], 0.f);
            #pragma unroll 1
            for (int a = 0; a < 32; a++) {
                const ulonglong2 w = *(const ulonglong2*)&sW2[a * 128 + lane * 4];
                #pragma unroll
                for (int t = 0; t < 8; t++) {
                    const ulonglong2 h2 = *(const ulonglong2*)&sH[t * 128 + a * 4];
                    fma2(x1p[t], h2.x, w.x);
                    fma2(x1p[t], h2.y, w.y);
                }
            }
            #pragma unroll
            for (int t = 0; t < 8; t++) sX[t * 32 + lane] = psum(x1p[t]);
        }
        __syncwarp();

        float* og = Out + (long long)b * 256;
        *(float4*)(og + lane * 8)     = *(float4*)&sX[lane * 8];
        *(float4*)(og + lane * 8 + 4) = *(float4*)&sX[lane * 8 + 4];
        __syncwarp();
    }
}

extern "C" void kernel_launch(void* const* d_in, const int* in_sizes, int n_in,
                              void* d_out, int out_size) {
    const float* X  = (const float*)d_in[0];
    const float* Wa = (const float*)d_in[1];
    const float* Wp = (const float*)d_in[2];
    const float* W1 = (const float*)d_in[3];
    const float* W2 = (const float*)d_in[4];
    float* Out = (float*)d_out;
    const int NB = in_sizes[0] / 256;

    cudaFuncSetAttribute(tblock_kernel,
                         cudaFuncAttributeMaxDynamicSharedMemorySize, SMEM_BYTES);
    tblock_kernel<<<GRID_BLOCKS, THREADS_PER_BLOCK, SMEM_BYTES>>>(
        X, Wa, Wp, W1, W2, Out, NB);
}